// round 7
// baseline (speedup 1.0000x reference)
#include <cuda_runtime.h>
#include <cstdint>

#define NCH         30
#define COORDW      5.0f
#define NOOBJW      0.5f
#define TPB         128
#define NWARPS      (TPB / 32)
#define CELLS_PW    32                          // cells per warp-tile
#define WTILE_FLOATS (CELLS_PW * NCH)           // 960 floats per array
#define WTILE_BYTES  (WTILE_FLOATS * 4)         // 3840 B per array
#define WSTAGE_FLOATS (2 * WTILE_FLOATS)        // data + labels = 1920 floats
#define WSTAGE_BYTES  (WSTAGE_FLOATS * 4)       // 7680 B
#define NSTAGE      3
#define SMEM_FLOATS (NWARPS * NSTAGE * WSTAGE_FLOATS)   // 23040
#define SMEM_BYTES  (SMEM_FLOATS * 4)                   // 92160 -> 2 blocks/SM
#define MAXGRID     1024

__device__ float        g_partials[MAXGRID];
__device__ unsigned int g_count = 0;

__device__ __forceinline__ uint32_t smem_u32(const void* p) {
    return (uint32_t)__cvta_generic_to_shared(p);
}
__device__ __forceinline__ void mbar_init(uint32_t mbar, uint32_t count) {
    asm volatile("mbarrier.init.shared.b64 [%0], %1;" :: "r"(mbar), "r"(count) : "memory");
}
__device__ __forceinline__ void mbar_expect_tx(uint32_t mbar, uint32_t bytes) {
    asm volatile("mbarrier.arrive.expect_tx.shared.b64 _, [%0], %1;"
                 :: "r"(mbar), "r"(bytes) : "memory");
}
__device__ __forceinline__ void mbar_wait(uint32_t mbar, uint32_t parity) {
    uint32_t done;
    asm volatile(
        "{\n\t"
        ".reg .pred p;\n\t"
        "mbarrier.try_wait.parity.acquire.cta.shared::cta.b64 p, [%1], %2;\n\t"
        "selp.b32 %0, 1, 0, p;\n\t"
        "}" : "=r"(done) : "r"(mbar), "r"(parity) : "memory");
    if (!done) {
        asm volatile(
            "{\n\t"
            ".reg .pred P1;\n\t"
            "WL_%=:\n\t"
            "mbarrier.try_wait.parity.acquire.cta.shared::cta.b64 P1, [%0], %1, 0x989680;\n\t"
            "@P1 bra.uni WD_%=;\n\t"
            "bra.uni WL_%=;\n\t"
            "WD_%=:\n\t"
            "}" :: "r"(mbar), "r"(parity) : "memory");
    }
}
__device__ __forceinline__ void bulk_g2s(uint32_t sdst, const void* gsrc,
                                         uint32_t bytes, uint32_t mbar) {
    asm volatile(
        "cp.async.bulk.shared::cta.global.mbarrier::complete_tx::bytes [%0], [%1], %2, [%3];"
        :: "r"(sdst), "l"(gsrc), "r"(bytes), "r"(mbar) : "memory");
}

__device__ __forceinline__ float warp_reduce(float v) {
    #pragma unroll
    for (int o = 16; o > 0; o >>= 1)
        v += __shfl_xor_sync(0xffffffffu, v, o);
    return v;
}

__device__ __forceinline__ void corners(float x, float y, float w, float h,
                                        float r, float c,
                                        float& x1, float& y1, float& x2, float& y2) {
    float cx = (x + c) * (1.0f / 7.0f);
    float cy = (y + r) * (1.0f / 7.0f);
    x1 = cx - w * 0.5f;
    y1 = cy - h * 0.5f;
    x2 = cx + w * 0.5f;
    y2 = cy + h * 0.5f;
}

__device__ __forceinline__ float iou(float ax1, float ay1, float ax2, float ay2,
                                     float bx1, float by1, float bx2, float by2) {
    float iw = fmaxf(fminf(ax2, bx2) - fmaxf(ax1, bx1), 0.0f);
    float ih = fmaxf(fminf(ay2, by2) - fmaxf(ay1, by1), 0.0f);
    float inter = iw * ih;
    float area_a = (ax2 - ax1) * (ay2 - ay1);
    float area_b = (bx2 - bx1) * (by2 - by1);
    float uni = area_a + area_b - inter;
    return (uni > 0.0f) ? __fdividef(inter, uni) : 0.0f;
}

__device__ __forceinline__ float cell_loss2(const float2* __restrict__ dp,
                                            const float2* __restrict__ lp,
                                            float r, float c) {
    float2 d01 = dp[0], d23 = dp[1], d45 = dp[2], d67 = dp[3], d89 = dp[4];
    float2 l01 = lp[0], l23 = lp[1], l45 = lp[2], l67 = lp[3], l89 = lp[4];

    float b1x1, b1y1, b1x2, b1y2;
    float b2x1, b2y1, b2x2, b2y2;
    float gx1,  gy1,  gx2,  gy2;
    corners(d01.x, d01.y, d23.x, d23.y, r, c, b1x1, b1y1, b1x2, b1y2);
    corners(d45.y, d67.x, d67.y, d89.x, r, c, b2x1, b2y1, b2x2, b2y2);
    corners(l01.x, l01.y, l23.x, l23.y, r, c, gx1,  gy1,  gx2,  gy2);

    float iou1 = iou(b1x1, b1y1, b1x2, b1y2, gx1, gy1, gx2, gy2);
    float iou2 = iou(b2x1, b2y1, b2x2, b2y2, gx1, gy1, gx2, gy2);
    bool resp1 = (iou1 >= iou2);

    float dx1 = d01.x - l01.x, dy1 = d01.y - l01.y;
    float dx2 = d45.y - l45.y, dy2 = d67.x - l67.x;
    float xy1 = dx1 * dx1 + dy1 * dy1;
    float xy2 = dx2 * dx2 + dy2 * dy2;

    float sw1 = sqrtf(d23.x) - sqrtf(l23.x);
    float sh1 = sqrtf(d23.y) - sqrtf(l23.y);
    float sw2 = sqrtf(d67.y) - sqrtf(l67.y);
    float sh2 = sqrtf(d89.x) - sqrtf(l89.x);
    float wh1 = sw1 * sw1 + sh1 * sh1;
    float wh2 = sw2 * sw2 + sh2 * sh2;

    float d4 = d45.x, d9 = d89.y;

    float co    = COORDW * (resp1 ? xy1 : xy2);
    float wh    = COORDW * (resp1 ? wh1 : wh2);
    float cdiff = resp1 ? (d4 - iou1) : (d9 - iou2);
    float confi = cdiff * cdiff;
    float nin   = NOOBJW * (resp1 ? d9 * d9 : d4 * d4);

    float cls = 0.0f;
    #pragma unroll
    for (int i = 5; i < 15; i++) {
        float2 a = dp[i], b = lp[i];
        float ex = a.x - b.x;
        float ey = a.y - b.y;
        cls += ex * ex + ey * ey;
    }

    float m = (l45.x == 1.0f) ? 1.0f : 0.0f;
    float obj_loss   = m * (co + wh + confi + nin + cls);
    float noobj_loss = (1.0f - m) * NOOBJW * (d4 * d4 + d9 * d9);
    return obj_loss + noobj_loss;
}

__global__ void __launch_bounds__(TPB, 2)
yolo_loss_warp_pipe(const float* __restrict__ data,
                    const float* __restrict__ labels,
                    float* __restrict__ out,
                    int ncells, float invB, int nwtiles) {
    extern __shared__ float smem[];   // [NWARPS][NSTAGE][WSTAGE_FLOATS]
    __shared__ __align__(8) uint64_t mbar_s[NWARPS][NSTAGE];
    __shared__ float sred[NWARPS];
    __shared__ bool  s_last;

    const int tid  = threadIdx.x;
    const int lane = tid & 31;
    const int warp = tid >> 5;
    const int gwarp = blockIdx.x * NWARPS + warp;            // global warp id
    const int nwarps_total = gridDim.x * NWARPS;

    float* wbase = smem + warp * NSTAGE * WSTAGE_FLOATS;

    uint32_t mb[NSTAGE];
    #pragma unroll
    for (int s = 0; s < NSTAGE; s++) mb[s] = smem_u32(&mbar_s[warp][s]);

    if (lane == 0) {
        #pragma unroll
        for (int s = 0; s < NSTAGE; s++) mbar_init(mb[s], 1);
    }
    __syncthreads();    // all warps' mbars initialized (cheap, once)

    // per-warp: issue one warp-tile's copies into stage s (lane 0 only)
    auto issue = [&](int wt, int s) {
        if (lane == 0) {
            uint32_t dst = smem_u32(wbase + s * WSTAGE_FLOATS);
            mbar_expect_tx(mb[s], 2 * WTILE_BYTES);
            bulk_g2s(dst,               (const char*)data   + (size_t)wt * WTILE_BYTES, WTILE_BYTES, mb[s]);
            bulk_g2s(dst + WTILE_BYTES, (const char*)labels + (size_t)wt * WTILE_BYTES, WTILE_BYTES, mb[s]);
        }
    };

    float acc = 0.0f;

    // prologue: depth-2 lookahead (full tiles only)
    {
        int t0 = gwarp;
        if (t0 < nwtiles && t0 * CELLS_PW + CELLS_PW <= ncells) issue(t0, 0);
        int t1 = t0 + nwarps_total;
        if (t1 < nwtiles && t1 * CELLS_PW + CELLS_PW <= ncells) issue(t1, 1);
    }

    int it = 0;
    for (int wt = gwarp; wt < nwtiles; wt += nwarps_total, it++) {
        bool full = (wt * CELLS_PW + CELLS_PW <= ncells);
        int s = it % NSTAGE;
        uint32_t parity = (uint32_t)((it / NSTAGE) & 1);

        int cell = wt * CELLS_PW + lane;
        int within = cell % 49;
        float r = (float)(within / 7);
        float c = (float)(within % 7);

        if (full) {
            mbar_wait(mb[s], parity);   // warp-local wait, no block sync
            const float* sd = wbase + s * WSTAGE_FLOATS;
            const float* sl = sd + WTILE_FLOATS;
            acc += cell_loss2(reinterpret_cast<const float2*>(sd) + lane * 15,
                              reinterpret_cast<const float2*>(sl) + lane * 15,
                              r, c);
        } else if (cell < ncells) {
            acc += cell_loss2(reinterpret_cast<const float2*>(data)   + (size_t)cell * 15,
                              reinterpret_cast<const float2*>(labels) + (size_t)cell * 15,
                              r, c);
        }
        __syncwarp();   // whole warp done reading stage s before refill

        int tnext = wt + 2 * nwarps_total;
        if (tnext < nwtiles && tnext * CELLS_PW + CELLS_PW <= ncells)
            issue(tnext, (it + 2) % NSTAGE);
    }

    // block reduction (deterministic)
    float v = warp_reduce(acc);
    if (lane == 0) sred[warp] = v;
    __syncthreads();
    if (tid == 0) {
        float s = sred[0] + sred[1] + sred[2] + sred[3];
        g_partials[blockIdx.x] = s;
        __threadfence();
        unsigned int t = atomicAdd(&g_count, 1u);
        s_last = (t == (unsigned int)(gridDim.x - 1));
    }
    __syncthreads();

    if (s_last) {
        float s = 0.0f;
        for (int i = tid; i < (int)gridDim.x; i += TPB)
            s += g_partials[i];
        float w = warp_reduce(s);
        if (lane == 0) sred[warp] = w;
        __syncthreads();
        if (tid == 0) {
            float tot = sred[0] + sred[1] + sred[2] + sred[3];
            out[0] = tot * invB;
            g_count = 0;   // reset for next graph replay
        }
    }
}

extern "C" void kernel_launch(void* const* d_in, const int* in_sizes, int n_in,
                              void* d_out, int out_size) {
    const float* data   = (const float*)d_in[0];
    const float* labels = (const float*)d_in[1];
    float* out = (float*)d_out;

    int total  = in_sizes[0];           // B*7*7*30
    int ncells = total / NCH;           // B*49
    int B      = ncells / 49;

    int nwtiles = (ncells + CELLS_PW - 1) / CELLS_PW;   // 12544 for B=8192
    int grid = 296;                                      // 148 SM x 2 blocks (92KB smem)
    if (grid * NWARPS > nwtiles) grid = (nwtiles + NWARPS - 1) / NWARPS;
    if (grid > MAXGRID) grid = MAXGRID;

    cudaFuncSetAttribute(yolo_loss_warp_pipe,
                         cudaFuncAttributeMaxDynamicSharedMemorySize, SMEM_BYTES);

    yolo_loss_warp_pipe<<<grid, TPB, SMEM_BYTES>>>(data, labels, out,
                                                   ncells, 1.0f / (float)B, nwtiles);
}